// round 15
// baseline (speedup 1.0000x reference)
#include <cuda_runtime.h>
#include <float.h>

#define N_REF   500000
#define N_PC    128
#define N_FEAT  2000
#define TOP_K   16

#define BLOCKS           592
#define THREADS          256
#define WARPS_PER_BLOCK  (THREADS / 32)
#define TOTAL_WARPS      (BLOCKS * WARPS_PER_BLOCK)   // 4736
#define N_CAND           (BLOCKS * TOP_K)             // 9472

#define PROJ_BLOCKS      200
#define FEAT_PER_BLOCK   (N_FEAT / PROJ_BLOCKS)       // 10
#define PROJ_Y           2
#define FEAT_PER_Y       (FEAT_PER_BLOCK / PROJ_Y)    // 5

#define MERGE_T          1024
#define MERGE_ROUNDS     ((N_CAND + MERGE_T - 1) / MERGE_T)   // 10
#define SURV_CAP         2048
#define MIN_PAD          608                          // 19 warps * 32
#define N_LISTS          19

// Scratch (no cudaMalloc allowed)
__device__ float g_qpart[PROJ_BLOCKS * N_PC];
__device__ float g_cand_d[N_CAND];
__device__ int   g_cand_i[N_CAND];
__device__ float g_bmin[BLOCKS];      // per-block minimum (compact, coalesced)

// ---------------------------------------------------------------------------
// Warp-distributed top-16 insert. Lane l (<16) holds the l-th smallest
// (dval, divx). v must be warp-uniform. ~7 instructions, no serial chain.
// ---------------------------------------------------------------------------
__device__ __forceinline__ void warp_insert16(float& dval, int& divx,
                                              float& kmax, int lane,
                                              float v, int id) {
    unsigned m = __ballot_sync(0xFFFFFFFFu, dval < v);
    int pos = __popc(m & 0xFFFFu);
    float up_d = __shfl_up_sync(0xFFFFFFFFu, dval, 1);
    int   up_i = __shfl_up_sync(0xFFFFFFFFu, divx, 1);
    if (lane >= pos) {
        dval = (lane == pos) ? v  : up_d;
        divx = (lane == pos) ? id : up_i;
    }
    kmax = __shfl_sync(0xFFFFFFFFu, dval, 15);
}

// ---------------------------------------------------------------------------
// Warp bitonic sort of 32 floats (ascending by lane), values only.
// ---------------------------------------------------------------------------
__device__ __forceinline__ void bitonic32v(float& v, int lane) {
    #pragma unroll
    for (int k = 2; k <= 32; k <<= 1) {
        #pragma unroll
        for (int j = k >> 1; j > 0; j >>= 1) {
            float ov = __shfl_xor_sync(0xFFFFFFFFu, v, j);
            bool up      = ((lane & k) == 0);
            bool lower   = ((lane & j) == 0);
            bool takeMin = (lower == up);
            bool sel = takeMin ? (ov < v) : (ov > v);
            v = sel ? ov : v;
        }
    }
}

// Bitonic MERGE of a 32-lane bitonic sequence -> ascending (5 stages).
__device__ __forceinline__ void bitonic_merge32(float& v, int lane) {
    #pragma unroll
    for (int j = 16; j > 0; j >>= 1) {
        float ov = __shfl_xor_sync(0xFFFFFFFFu, v, j);
        v = ((lane & j) == 0) ? fminf(v, ov) : fmaxf(v, ov);
    }
}

// ---------------------------------------------------------------------------
// Kernel A: partial query projection. 200 blocks x (128,2): block b covers
// 10 features, 5 per y-slice -> spans all 148 SMs instead of 50.
// ---------------------------------------------------------------------------
__global__ void __launch_bounds__(N_PC * PROJ_Y)
project_partial(const float* __restrict__ data_in,
                const float* __restrict__ tmat) {
    const int j  = threadIdx.x;          // 0..127 (PC index)
    const int y  = threadIdx.y;          // 0..1
    const int b  = blockIdx.x;
    const int k0 = b * FEAT_PER_BLOCK + y * FEAT_PER_Y;

    float acc = 0.0f;
    #pragma unroll
    for (int k = k0; k < k0 + FEAT_PER_Y; k++)
        acc += data_in[k] * tmat[k * N_PC + j];   // coalesced over j

    __shared__ float sred[PROJ_Y][N_PC];
    sred[y][j] = acc;
    __syncthreads();
    if (y == 0)
        g_qpart[b * N_PC + j] = sred[0][j] + sred[1][j];
}

// ---------------------------------------------------------------------------
// Kernel B: [prologue] reduce 200 projection partials -> shared (L2-hot,
//   4 independent accumulators, pipelined); [mainloop/tail] BYTE-IDENTICAL
//   to R13/R14 best.
// ---------------------------------------------------------------------------
__global__ void __launch_bounds__(THREADS)
dist_topk_kernel(const float* __restrict__ ref) {
    const int tid  = threadIdx.x;
    const int lane = tid & 31;
    const int wid  = tid >> 5;
    const int gw   = blockIdx.x * WARPS_PER_BLOCK + wid;

    // ---- prologue: finish query projection into shared ----
    __shared__ __align__(16) float sq[N_PC];
    if (tid < N_PC) {
        float a0 = 0.0f, a1 = 0.0f, a2 = 0.0f, a3 = 0.0f;
        #pragma unroll
        for (int b = 0; b < PROJ_BLOCKS; b += 4) {
            a0 += g_qpart[(b + 0) * N_PC + tid];
            a1 += g_qpart[(b + 1) * N_PC + tid];
            a2 += g_qpart[(b + 2) * N_PC + tid];
            a3 += g_qpart[(b + 3) * N_PC + tid];
        }
        sq[tid] = (a0 + a1) + (a2 + a3);
    }
    __syncthreads();
    const float4 q = reinterpret_cast<const float4*>(sq)[lane];

    const int chunk = (N_REF + TOTAL_WARPS - 1) / TOTAL_WARPS;  // 106
    int start = gw * chunk;
    int end   = start + chunk;
    if (start > N_REF) start = N_REF;
    if (end   > N_REF) end   = N_REF;

    float dval = FLT_MAX;
    int   divx = 0;
    float kmax = FLT_MAX;

    const float4* __restrict__ ref4 = reinterpret_cast<const float4*>(ref);

    const int nIter = (end - start) / 4;
    int r = start;

    float4 A0, A1, A2, A3;
    if (nIter > 0) {
        A0 = __ldcs(ref4 + (size_t)(r + 0) * (N_PC / 4) + lane);
        A1 = __ldcs(ref4 + (size_t)(r + 1) * (N_PC / 4) + lane);
        A2 = __ldcs(ref4 + (size_t)(r + 2) * (N_PC / 4) + lane);
        A3 = __ldcs(ref4 + (size_t)(r + 3) * (N_PC / 4) + lane);
    }

    for (int it = 0; it < nIter; it++) {
        float4 B0, B1, B2, B3;
        if (it + 1 < nIter) {
            int rn = r + 4;
            B0 = __ldcs(ref4 + (size_t)(rn + 0) * (N_PC / 4) + lane);
            B1 = __ldcs(ref4 + (size_t)(rn + 1) * (N_PC / 4) + lane);
            B2 = __ldcs(ref4 + (size_t)(rn + 2) * (N_PC / 4) + lane);
            B3 = __ldcs(ref4 + (size_t)(rn + 3) * (N_PC / 4) + lane);
        }

        float s0 = fabsf(A0.x - q.x) + fabsf(A0.y - q.y) + fabsf(A0.z - q.z) + fabsf(A0.w - q.w);
        float s1 = fabsf(A1.x - q.x) + fabsf(A1.y - q.y) + fabsf(A1.z - q.z) + fabsf(A1.w - q.w);
        float s2 = fabsf(A2.x - q.x) + fabsf(A2.y - q.y) + fabsf(A2.z - q.z) + fabsf(A2.w - q.w);
        float s3 = fabsf(A3.x - q.x) + fabsf(A3.y - q.y) + fabsf(A3.z - q.z) + fabsf(A3.w - q.w);

        #pragma unroll
        for (int off = 16; off > 0; off >>= 1) {
            s0 += __shfl_xor_sync(0xFFFFFFFFu, s0, off);
            s1 += __shfl_xor_sync(0xFFFFFFFFu, s1, off);
            s2 += __shfl_xor_sync(0xFFFFFFFFu, s2, off);
            s3 += __shfl_xor_sync(0xFFFFFFFFu, s3, off);
        }
        if (s0 < kmax) warp_insert16(dval, divx, kmax, lane, s0, r + 0);
        if (s1 < kmax) warp_insert16(dval, divx, kmax, lane, s1, r + 1);
        if (s2 < kmax) warp_insert16(dval, divx, kmax, lane, s2, r + 2);
        if (s3 < kmax) warp_insert16(dval, divx, kmax, lane, s3, r + 3);

        A0 = B0; A1 = B1; A2 = B2; A3 = B3;
        r += 4;
    }
    for (; r < end; r++) {
        float4 a0 = __ldcs(ref4 + (size_t)r * (N_PC / 4) + lane);
        float s0 = fabsf(a0.x - q.x) + fabsf(a0.y - q.y) + fabsf(a0.z - q.z) + fabsf(a0.w - q.w);
        #pragma unroll
        for (int off = 16; off > 0; off >>= 1)
            s0 += __shfl_xor_sync(0xFFFFFFFFu, s0, off);
        if (s0 < kmax) warp_insert16(dval, divx, kmax, lane, s0, r);
    }

    __shared__ float sbd[WARPS_PER_BLOCK * TOP_K];   // 128
    __shared__ int   sbi[WARPS_PER_BLOCK * TOP_K];
    if (lane < TOP_K) {
        sbd[wid * TOP_K + lane] = dval;
        sbi[wid * TOP_K + lane] = divx;
    }
    __syncthreads();

    if (tid < 128) {
        float v  = sbd[tid];
        int   id = sbi[tid];
        int rank = 0;
        #pragma unroll 8
        for (int j = 0; j < 128; j++) {
            float o = sbd[j];
            rank += (o < v) || (o == v && j < tid);
        }
        if (rank < TOP_K) {
            g_cand_d[blockIdx.x * TOP_K + rank] = v;
            g_cand_i[blockIdx.x * TOP_K + rank] = id;
        }
        if (rank == 0) g_bmin[blockIdx.x] = v;   // compact block minimum
    }
}

// ---------------------------------------------------------------------------
// Kernel C (UNCHANGED from R13): merge. Loads hoisted; tau = exact 16th of
// 592 block minima via bitonic merge tree; warp-aggregated filter append;
// rank-select + gather + mean.
// ---------------------------------------------------------------------------
__global__ void __launch_bounds__(MERGE_T)
merge_kernel(const float* __restrict__ psuedo,
             float* __restrict__ out) {
    const int tid  = threadIdx.x;
    const int lane = tid & 31;
    const int wid  = tid >> 5;

    __shared__ float s_a[N_LISTS * TOP_K];   // 304
    __shared__ float s_b[N_LISTS * TOP_K];
    __shared__ int   s_cnt;
    __shared__ float s_d[SURV_CAP];
    __shared__ int   s_c[SURV_CAP];
    __shared__ float s_sel[TOP_K];

    if (tid == 0) s_cnt = 0;

    // ---- issue ALL global loads up front ----
    float vb[MERGE_ROUNDS];
    #pragma unroll
    for (int t = 0; t < MERGE_ROUNDS; t++) {
        int c = tid + t * MERGE_T;
        vb[t] = (c < N_CAND) ? g_cand_d[c] : FLT_MAX;
    }
    float vmin = (tid < BLOCKS) ? g_bmin[tid] : FLT_MAX;   // coalesced

    // ---- phase 1a: per-warp bitonic sort-32, keep sorted 16 ----
    if (tid < MIN_PAD) {               // 19 full warps
        bitonic32v(vmin, lane);
        if (lane < TOP_K) s_a[wid * TOP_K + lane] = vmin;
    }
    __syncthreads();

    // ---- phase 1b: bitonic merge tree, 19 lists -> 1 (ping-pong) ----
    {
        float* src = s_a;
        float* dst = s_b;
        int n = N_LISTS;
        while (n > 1) {
            int half = n >> 1;
            if (wid < half) {
                float v = (lane < TOP_K)
                        ? src[(2 * wid) * TOP_K + lane]
                        : src[(2 * wid + 1) * TOP_K + (31 - lane)];
                bitonic_merge32(v, lane);
                if (lane < TOP_K) dst[wid * TOP_K + lane] = v;
            } else if ((n & 1) && wid == half) {
                if (lane < TOP_K)
                    dst[half * TOP_K + lane] = src[(n - 1) * TOP_K + lane];
            }
            __syncthreads();
            n = half + (n & 1);
            float* tmp = src; src = dst; dst = tmp;
        }
        if (tid == 0) s_sel[0] = src[TOP_K - 1];   // stash tau
    }
    __syncthreads();
    const float tau = s_sel[0];

    // ---- phase 2: threshold filter with warp-aggregated append ----
    #pragma unroll
    for (int t = 0; t < MERGE_ROUNDS; t++) {
        int c = tid + t * MERGE_T;
        bool pred = (vb[t] <= tau);
        unsigned m = __ballot_sync(0xFFFFFFFFu, pred);
        if (m) {
            int base = 0;
            if (lane == 0) base = atomicAdd(&s_cnt, __popc(m));
            base = __shfl_sync(0xFFFFFFFFu, base, 0);
            if (pred) {
                int pos = base + __popc(m & ((1u << lane) - 1u));
                if (pos < SURV_CAP) {
                    s_d[pos] = vb[t];
                    s_c[pos] = c;
                }
            }
        }
    }
    __syncthreads();
    const int cnt = (s_cnt < SURV_CAP) ? s_cnt : SURV_CAP;

    // ---- phase 3: rank-select top-16 of survivors, gather, mean ----
    if (tid < cnt) {
        float v = s_d[tid];
        int   c = s_c[tid];
        int rank = 0;
        for (int j = 0; j < cnt; j++) {
            float o = s_d[j];
            rank += (o < v) || (o == v && s_c[j] < c);
        }
        if (rank < TOP_K) s_sel[rank] = psuedo[g_cand_i[c]];
    }
    __syncthreads();

    if (tid < 32) {
        float v = (tid < TOP_K) ? s_sel[tid] : 0.0f;
        #pragma unroll
        for (int off = 16; off > 0; off >>= 1)
            v += __shfl_xor_sync(0xFFFFFFFFu, v, off);
        if (tid == 0) out[0] = v * (1.0f / TOP_K);
    }
}

// ---------------------------------------------------------------------------
// Launch (3 kernels)
// ---------------------------------------------------------------------------
extern "C" void kernel_launch(void* const* d_in, const int* in_sizes, int n_in,
                              void* d_out, int out_size) {
    const float* data_in = (const float*)d_in[0];
    const float* tmat    = (const float*)d_in[1];
    const float* ref     = (const float*)d_in[2];
    const float* psuedo  = (const float*)d_in[3];
    float* out = (float*)d_out;

    dim3 pb(N_PC, PROJ_Y);
    project_partial<<<PROJ_BLOCKS, pb>>>(data_in, tmat);
    dist_topk_kernel<<<BLOCKS, THREADS>>>(ref);
    merge_kernel<<<1, MERGE_T>>>(psuedo, out);
}

// round 16
// speedup vs baseline: 1.0225x; 1.0225x over previous
#include <cuda_runtime.h>
#include <float.h>

#define N_REF   500000
#define N_PC    128
#define N_FEAT  2000
#define TOP_K   16

#define BLOCKS           592
#define THREADS          256
#define WARPS_PER_BLOCK  (THREADS / 32)
#define TOTAL_WARPS      (BLOCKS * WARPS_PER_BLOCK)   // 4736
#define N_CAND           (BLOCKS * TOP_K)             // 9472

#define PROJ_BLOCKS      50
#define FEAT_PER_BLOCK   (N_FEAT / PROJ_BLOCKS)       // 40
#define FEAT_PER_Y       (FEAT_PER_BLOCK / 2)         // 20 (2 y-slices)

#define MERGE_T          1024
#define MERGE_ROUNDS     ((N_CAND + MERGE_T - 1) / MERGE_T)   // 10
#define SURV_CAP         2048
#define MIN_PAD          608                          // 19 warps * 32
#define N_LISTS          19

// Scratch (no cudaMalloc allowed)
__device__ float g_qpart[PROJ_BLOCKS * N_PC];
__device__ float g_cand_d[N_CAND];
__device__ int   g_cand_i[N_CAND];
__device__ float g_bmin[BLOCKS];      // per-block minimum (compact, coalesced)
__device__ int   g_pflag;             // proj-done counter; reset by merge_kernel

// ---------------------------------------------------------------------------
// Warp-distributed top-16 insert. Lane l (<16) holds the l-th smallest
// (dval, divx). v must be warp-uniform. ~7 instructions, no serial chain.
// ---------------------------------------------------------------------------
__device__ __forceinline__ void warp_insert16(float& dval, int& divx,
                                              float& kmax, int lane,
                                              float v, int id) {
    unsigned m = __ballot_sync(0xFFFFFFFFu, dval < v);
    int pos = __popc(m & 0xFFFFu);
    float up_d = __shfl_up_sync(0xFFFFFFFFu, dval, 1);
    int   up_i = __shfl_up_sync(0xFFFFFFFFu, divx, 1);
    if (lane >= pos) {
        dval = (lane == pos) ? v  : up_d;
        divx = (lane == pos) ? id : up_i;
    }
    kmax = __shfl_sync(0xFFFFFFFFu, dval, 15);
}

// ---------------------------------------------------------------------------
// Warp bitonic sort of 32 floats (ascending by lane), values only.
// ---------------------------------------------------------------------------
__device__ __forceinline__ void bitonic32v(float& v, int lane) {
    #pragma unroll
    for (int k = 2; k <= 32; k <<= 1) {
        #pragma unroll
        for (int j = k >> 1; j > 0; j >>= 1) {
            float ov = __shfl_xor_sync(0xFFFFFFFFu, v, j);
            bool up      = ((lane & k) == 0);
            bool lower   = ((lane & j) == 0);
            bool takeMin = (lower == up);
            bool sel = takeMin ? (ov < v) : (ov > v);
            v = sel ? ov : v;
        }
    }
}

// Bitonic MERGE of a 32-lane bitonic sequence -> ascending (5 stages).
__device__ __forceinline__ void bitonic_merge32(float& v, int lane) {
    #pragma unroll
    for (int j = 16; j > 0; j >>= 1) {
        float ov = __shfl_xor_sync(0xFFFFFFFFu, v, j);
        v = ((lane & j) == 0) ? fminf(v, ov) : fmaxf(v, ov);
    }
}

// ---------------------------------------------------------------------------
// Kernel B (FUSED): grid = 592 = 148 SMs x 4 CTAs, forced co-resident via
// __launch_bounds__(256, 4) -> the grid-wide flag barrier cannot deadlock.
//   [stage 0] blocks 0..49 compute the 50x128 projection partials (same
//     layout as the old proj kernel); release via threadfence + atomicAdd.
//   [barrier] tid 0 of every block spins on g_pflag == 50 (volatile loads).
//   [prologue] R14's measured-good 50-partial reduce -> shared query.
//   [mainloop/tail] BYTE-IDENTICAL to R13/R14 best.
// ---------------------------------------------------------------------------
__global__ void __launch_bounds__(THREADS, 4)
dist_topk_kernel(const float* __restrict__ ref,
                 const float* __restrict__ data_in,
                 const float* __restrict__ tmat) {
    const int tid  = threadIdx.x;
    const int lane = tid & 31;
    const int wid  = tid >> 5;
    const int gw   = blockIdx.x * WARPS_PER_BLOCK + wid;

    // ---- stage 0: projection partials (blocks 0..49) ----
    if (blockIdx.x < PROJ_BLOCKS) {
        const int j = tid & (N_PC - 1);      // 0..127
        const int y = tid >> 7;              // 0..1
        const int k0 = blockIdx.x * FEAT_PER_BLOCK + y * FEAT_PER_Y;
        float acc = 0.0f;
        #pragma unroll
        for (int k = k0; k < k0 + FEAT_PER_Y; k++)
            acc += data_in[k] * tmat[k * N_PC + j];   // coalesced over j
        __shared__ float sred[2][N_PC];
        sred[y][j] = acc;
        __syncthreads();
        if (y == 0)
            g_qpart[blockIdx.x * N_PC + j] = sred[0][j] + sred[1][j];
        __threadfence();                      // release partials
        __syncthreads();
        if (tid == 0) atomicAdd(&g_pflag, 1);
    }

    // ---- grid barrier: wait for all 50 projection slices ----
    if (tid == 0) {
        while (*((volatile int*)&g_pflag) < PROJ_BLOCKS) { }
    }
    __syncthreads();
    __threadfence();                          // acquire partials

    // ---- prologue: reduce 50 projection partials -> shared query ----
    __shared__ __align__(16) float sq[N_PC];
    if (tid < N_PC) {
        float acc = 0.0f;
        #pragma unroll
        for (int b = 0; b < PROJ_BLOCKS; b++)
            acc += g_qpart[b * N_PC + tid];
        sq[tid] = acc;
    }
    __syncthreads();
    const float4 q = reinterpret_cast<const float4*>(sq)[lane];

    const int chunk = (N_REF + TOTAL_WARPS - 1) / TOTAL_WARPS;  // 106
    int start = gw * chunk;
    int end   = start + chunk;
    if (start > N_REF) start = N_REF;
    if (end   > N_REF) end   = N_REF;

    float dval = FLT_MAX;
    int   divx = 0;
    float kmax = FLT_MAX;

    const float4* __restrict__ ref4 = reinterpret_cast<const float4*>(ref);

    const int nIter = (end - start) / 4;
    int r = start;

    float4 A0, A1, A2, A3;
    if (nIter > 0) {
        A0 = __ldcs(ref4 + (size_t)(r + 0) * (N_PC / 4) + lane);
        A1 = __ldcs(ref4 + (size_t)(r + 1) * (N_PC / 4) + lane);
        A2 = __ldcs(ref4 + (size_t)(r + 2) * (N_PC / 4) + lane);
        A3 = __ldcs(ref4 + (size_t)(r + 3) * (N_PC / 4) + lane);
    }

    for (int it = 0; it < nIter; it++) {
        float4 B0, B1, B2, B3;
        if (it + 1 < nIter) {
            int rn = r + 4;
            B0 = __ldcs(ref4 + (size_t)(rn + 0) * (N_PC / 4) + lane);
            B1 = __ldcs(ref4 + (size_t)(rn + 1) * (N_PC / 4) + lane);
            B2 = __ldcs(ref4 + (size_t)(rn + 2) * (N_PC / 4) + lane);
            B3 = __ldcs(ref4 + (size_t)(rn + 3) * (N_PC / 4) + lane);
        }

        float s0 = fabsf(A0.x - q.x) + fabsf(A0.y - q.y) + fabsf(A0.z - q.z) + fabsf(A0.w - q.w);
        float s1 = fabsf(A1.x - q.x) + fabsf(A1.y - q.y) + fabsf(A1.z - q.z) + fabsf(A1.w - q.w);
        float s2 = fabsf(A2.x - q.x) + fabsf(A2.y - q.y) + fabsf(A2.z - q.z) + fabsf(A2.w - q.w);
        float s3 = fabsf(A3.x - q.x) + fabsf(A3.y - q.y) + fabsf(A3.z - q.z) + fabsf(A3.w - q.w);

        #pragma unroll
        for (int off = 16; off > 0; off >>= 1) {
            s0 += __shfl_xor_sync(0xFFFFFFFFu, s0, off);
            s1 += __shfl_xor_sync(0xFFFFFFFFu, s1, off);
            s2 += __shfl_xor_sync(0xFFFFFFFFu, s2, off);
            s3 += __shfl_xor_sync(0xFFFFFFFFu, s3, off);
        }
        if (s0 < kmax) warp_insert16(dval, divx, kmax, lane, s0, r + 0);
        if (s1 < kmax) warp_insert16(dval, divx, kmax, lane, s1, r + 1);
        if (s2 < kmax) warp_insert16(dval, divx, kmax, lane, s2, r + 2);
        if (s3 < kmax) warp_insert16(dval, divx, kmax, lane, s3, r + 3);

        A0 = B0; A1 = B1; A2 = B2; A3 = B3;
        r += 4;
    }
    for (; r < end; r++) {
        float4 a0 = __ldcs(ref4 + (size_t)r * (N_PC / 4) + lane);
        float s0 = fabsf(a0.x - q.x) + fabsf(a0.y - q.y) + fabsf(a0.z - q.z) + fabsf(a0.w - q.w);
        #pragma unroll
        for (int off = 16; off > 0; off >>= 1)
            s0 += __shfl_xor_sync(0xFFFFFFFFu, s0, off);
        if (s0 < kmax) warp_insert16(dval, divx, kmax, lane, s0, r);
    }

    __shared__ float sbd[WARPS_PER_BLOCK * TOP_K];   // 128
    __shared__ int   sbi[WARPS_PER_BLOCK * TOP_K];
    if (lane < TOP_K) {
        sbd[wid * TOP_K + lane] = dval;
        sbi[wid * TOP_K + lane] = divx;
    }
    __syncthreads();

    if (tid < 128) {
        float v  = sbd[tid];
        int   id = sbi[tid];
        int rank = 0;
        #pragma unroll 8
        for (int j = 0; j < 128; j++) {
            float o = sbd[j];
            rank += (o < v) || (o == v && j < tid);
        }
        if (rank < TOP_K) {
            g_cand_d[blockIdx.x * TOP_K + rank] = v;
            g_cand_i[blockIdx.x * TOP_K + rank] = id;
        }
        if (rank == 0) g_bmin[blockIdx.x] = v;   // compact block minimum
    }
}

// ---------------------------------------------------------------------------
// Kernel C (merge, UNCHANGED logic from R13/R14 + flag reset for replay).
// ---------------------------------------------------------------------------
__global__ void __launch_bounds__(MERGE_T)
merge_kernel(const float* __restrict__ psuedo,
             float* __restrict__ out) {
    const int tid  = threadIdx.x;
    const int lane = tid & 31;
    const int wid  = tid >> 5;

    if (tid == 0) g_pflag = 0;         // reset barrier for next graph replay

    __shared__ float s_a[N_LISTS * TOP_K];   // 304
    __shared__ float s_b[N_LISTS * TOP_K];
    __shared__ int   s_cnt;
    __shared__ float s_d[SURV_CAP];
    __shared__ int   s_c[SURV_CAP];
    __shared__ float s_sel[TOP_K];

    if (tid == 0) s_cnt = 0;

    // ---- issue ALL global loads up front ----
    float vb[MERGE_ROUNDS];
    #pragma unroll
    for (int t = 0; t < MERGE_ROUNDS; t++) {
        int c = tid + t * MERGE_T;
        vb[t] = (c < N_CAND) ? g_cand_d[c] : FLT_MAX;
    }
    float vmin = (tid < BLOCKS) ? g_bmin[tid] : FLT_MAX;   // coalesced

    // ---- phase 1a: per-warp bitonic sort-32, keep sorted 16 ----
    if (tid < MIN_PAD) {               // 19 full warps
        bitonic32v(vmin, lane);
        if (lane < TOP_K) s_a[wid * TOP_K + lane] = vmin;
    }
    __syncthreads();

    // ---- phase 1b: bitonic merge tree, 19 lists -> 1 (ping-pong) ----
    {
        float* src = s_a;
        float* dst = s_b;
        int n = N_LISTS;
        while (n > 1) {
            int half = n >> 1;
            if (wid < half) {
                float v = (lane < TOP_K)
                        ? src[(2 * wid) * TOP_K + lane]
                        : src[(2 * wid + 1) * TOP_K + (31 - lane)];
                bitonic_merge32(v, lane);
                if (lane < TOP_K) dst[wid * TOP_K + lane] = v;
            } else if ((n & 1) && wid == half) {
                if (lane < TOP_K)
                    dst[half * TOP_K + lane] = src[(n - 1) * TOP_K + lane];
            }
            __syncthreads();
            n = half + (n & 1);
            float* tmp = src; src = dst; dst = tmp;
        }
        if (tid == 0) s_sel[0] = src[TOP_K - 1];   // stash tau
    }
    __syncthreads();
    const float tau = s_sel[0];

    // ---- phase 2: threshold filter with warp-aggregated append ----
    #pragma unroll
    for (int t = 0; t < MERGE_ROUNDS; t++) {
        int c = tid + t * MERGE_T;
        bool pred = (vb[t] <= tau);
        unsigned m = __ballot_sync(0xFFFFFFFFu, pred);
        if (m) {
            int base = 0;
            if (lane == 0) base = atomicAdd(&s_cnt, __popc(m));
            base = __shfl_sync(0xFFFFFFFFu, base, 0);
            if (pred) {
                int pos = base + __popc(m & ((1u << lane) - 1u));
                if (pos < SURV_CAP) {
                    s_d[pos] = vb[t];
                    s_c[pos] = c;
                }
            }
        }
    }
    __syncthreads();
    const int cnt = (s_cnt < SURV_CAP) ? s_cnt : SURV_CAP;

    // ---- phase 3: rank-select top-16 of survivors, gather, mean ----
    if (tid < cnt) {
        float v = s_d[tid];
        int   c = s_c[tid];
        int rank = 0;
        for (int j = 0; j < cnt; j++) {
            float o = s_d[j];
            rank += (o < v) || (o == v && s_c[j] < c);
        }
        if (rank < TOP_K) s_sel[rank] = psuedo[g_cand_i[c]];
    }
    __syncthreads();

    if (tid < 32) {
        float v = (tid < TOP_K) ? s_sel[tid] : 0.0f;
        #pragma unroll
        for (int off = 16; off > 0; off >>= 1)
            v += __shfl_xor_sync(0xFFFFFFFFu, v, off);
        if (tid == 0) out[0] = v * (1.0f / TOP_K);
    }
}

// ---------------------------------------------------------------------------
// Launch (2 kernels)
// ---------------------------------------------------------------------------
extern "C" void kernel_launch(void* const* d_in, const int* in_sizes, int n_in,
                              void* d_out, int out_size) {
    const float* data_in = (const float*)d_in[0];
    const float* tmat    = (const float*)d_in[1];
    const float* ref     = (const float*)d_in[2];
    const float* psuedo  = (const float*)d_in[3];
    float* out = (float*)d_out;

    dist_topk_kernel<<<BLOCKS, THREADS>>>(ref, data_in, tmat);
    merge_kernel<<<1, MERGE_T>>>(psuedo, out);
}